// round 4
// baseline (speedup 1.0000x reference)
#include <cuda_runtime.h>
#include <cuda_bf16.h>
#include <cstdint>
#include <cstddef>

#define B_ 8
#define N_ 16384
#define S_ 1024
#define K_ 32
#define NCC (B_*S_)                 // 8192 centers
#define NROWS (NCC*K_)              // 262144 grouped rows
#define R2_ 0.04f
#define STAT_BLKS 2048
#define ROWS_PER_STAT (NROWS/STAT_BLKS)   // 128

// ---------------- device scratch (static; allocation APIs are banned) ----------------
__device__ __align__(16) float g_centers[NCC*3];
__device__ int                 g_nbr[NROWS];
__device__ __align__(16) float g_h1[(size_t)NROWS*64];    // 64 MiB (reused sem/geo)
__device__ __align__(16) float g_h2[(size_t)NROWS*128];   // 128 MiB (reused sem/geo)
__device__ __align__(16) float g_part[STAT_BLKS*128*2];   // per-block (sum,sumsq)
__device__ __align__(16) float g_a[128];                  // BN scale
__device__ __align__(16) float g_c[128];                  // BN shift

// =====================================================================
// FPS: one CTA per batch. pos SoA in dynamic SMEM, dist in registers.
// =====================================================================
__global__ __launch_bounds__(1024, 1)
void fps_kernel(const float* __restrict__ pos) {
    extern __shared__ float sm[];
    float* sx = sm;
    float* sy = sm + N_;
    float* sz = sm + 2 * N_;
    __shared__ unsigned long long wkeys[32];
    __shared__ int sFar;

    const int b = blockIdx.x;
    const int tid = threadIdx.x;
    const float* p = pos + (size_t)b * N_ * 3;
    for (int t = tid; t < N_ * 3; t += 1024) {
        float v = p[t];
        int pt = t / 3, c = t - pt * 3;
        if (c == 0) sx[pt] = v; else if (c == 1) sy[pt] = v; else sz[pt] = v;
    }
    __syncthreads();

    float dist[16];
#pragma unroll
    for (int j = 0; j < 16; j++) dist[j] = 1e10f;
    float cx = sx[0], cy = sy[0], cz = sz[0];

    for (int s = 0; s < S_; s++) {
        if (tid == 0) {
            size_t cc = (size_t)b * S_ + s;
            g_centers[cc*3+0] = cx; g_centers[cc*3+1] = cy; g_centers[cc*3+2] = cz;
        }
        float best = -1.0f; int bidx = 0;
#pragma unroll
        for (int j = 0; j < 16; j++) {
            int pi = j * 1024 + tid;
            float dx = sx[pi] - cx, dy = sy[pi] - cy, dz = sz[pi] - cz;
            float d  = fmaf(dz, dz, fmaf(dy, dy, dx * dx));
            float nd = fminf(dist[j], d);
            dist[j]  = nd;
            if (nd > best) { best = nd; bidx = pi; }
        }
        // key: hi32 = float bits of best (positive floats are order-isomorphic),
        //      lo32 = N - idx so that ties pick the SMALLEST index (JAX argmax).
        unsigned long long key =
            ((unsigned long long)__float_as_uint(best) << 32) | (unsigned)(N_ - bidx);
#pragma unroll
        for (int o = 16; o; o >>= 1) {
            unsigned long long k2 = __shfl_down_sync(0xFFFFFFFFu, key, o);
            if (k2 > key) key = k2;
        }
        if ((tid & 31) == 0) wkeys[tid >> 5] = key;
        __syncthreads();
        if (tid < 32) {
            key = wkeys[tid];
#pragma unroll
            for (int o = 16; o; o >>= 1) {
                unsigned long long k2 = __shfl_down_sync(0xFFFFFFFFu, key, o);
                if (k2 > key) key = k2;
            }
            if (tid == 0) sFar = N_ - (int)(unsigned)(key & 0xFFFFFFFFull);
        }
        __syncthreads();
        int far = sFar;
        cx = sx[far]; cy = sy[far]; cz = sz[far];
    }
}

// =====================================================================
// Ball query: one warp per center, ascending index scan, early exit.
// Matches sort-then-take-first-K semantics; pads with first hit.
// =====================================================================
__global__ __launch_bounds__(256)
void ballquery_kernel(const float* __restrict__ pos) {
    __shared__ int buf[8][32];
    const int wloc = threadIdx.x >> 5;
    const int lane = threadIdx.x & 31;
    const int cc = blockIdx.x * 8 + wloc;          // 0..8191
    const int b = cc >> 10;
    const float* p = pos + (size_t)b * N_ * 3;
    const float cx = g_centers[cc*3], cy = g_centers[cc*3+1], cz = g_centers[cc*3+2];

    int count = 0, first = 0;
    bool haveFirst = false;
    for (int base = 0; base < N_; base += 32) {
        int j = base + lane;
        float x = p[j*3], y = p[j*3+1], z = p[j*3+2];
        float dx = cx - x, dy = cy - y, dz = cz - z;
        float d = fmaf(dz, dz, fmaf(dy, dy, dx * dx));
        bool in = (d <= R2_);
        unsigned m = __ballot_sync(0xFFFFFFFFu, in);
        if (m) {
            if (!haveFirst) { first = base + __ffs(m) - 1; haveFirst = true; }
            int slot = count + __popc(m & ((1u << lane) - 1u));
            if (in && slot < 32) buf[wloc][slot] = j;
            count += __popc(m);
            if (count >= 32) break;
        }
    }
    __syncwarp();
    int v = (lane < count) ? buf[wloc][lane] : first;
    g_nbr[(size_t)cc * 32 + lane] = v;
}

// =====================================================================
// conv1: gather + X[64rows x CIN] @ W[CIN x 64] + bias -> raw h1.
// CIN=64 (sem: gather feat) or CIN=6 (geo: center||pos).
// =====================================================================
template<int CIN, bool GEO>
__global__ __launch_bounds__(256)
void conv1_kernel(const float* __restrict__ feat, const float* __restrict__ pos,
                  const float* __restrict__ W, const float* __restrict__ bias) {
    __shared__ float Xs[64 * CIN];
    __shared__ float Ws[CIN * 64];
    const int row0 = blockIdx.x * 64;
    const int tid = threadIdx.x;

    for (int i = tid; i < CIN * 64; i += 256) Ws[i] = W[i];

    if (!GEO) {
        for (int i = tid; i < 64 * CIN; i += 256) {
            int r = i / CIN, c = i - r * CIN;
            int row = row0 + r;
            int j = g_nbr[row];
            int b = row >> 15;
            Xs[i] = feat[((size_t)b * N_ + j) * 64 + c];
        }
    } else {
        for (int i = tid; i < 64 * CIN; i += 256) {
            int r = i / CIN, c = i - r * CIN;
            int row = row0 + r;
            int cc = row >> 5;
            if (c < 3) {
                Xs[i] = g_centers[cc * 3 + c];
            } else {
                int j = g_nbr[row];
                int b = row >> 15;
                Xs[i] = pos[((size_t)b * N_ + j) * 3 + (c - 3)];
            }
        }
    }
    __syncthreads();

    const int ty = tid >> 4, tx = tid & 15;
    float acc[4][4];
#pragma unroll
    for (int i = 0; i < 4; i++)
#pragma unroll
        for (int j = 0; j < 4; j++) acc[i][j] = 0.0f;

#pragma unroll
    for (int k = 0; k < CIN; k++) {
        float xv[4];
#pragma unroll
        for (int i = 0; i < 4; i++) xv[i] = Xs[(ty * 4 + i) * CIN + k];
        float4 wv = *(const float4*)&Ws[k * 64 + tx * 4];
#pragma unroll
        for (int i = 0; i < 4; i++) {
            acc[i][0] = fmaf(xv[i], wv.x, acc[i][0]);
            acc[i][1] = fmaf(xv[i], wv.y, acc[i][1]);
            acc[i][2] = fmaf(xv[i], wv.z, acc[i][2]);
            acc[i][3] = fmaf(xv[i], wv.w, acc[i][3]);
        }
    }
#pragma unroll
    for (int i = 0; i < 4; i++) {
        int row = row0 + ty * 4 + i;
#pragma unroll
        for (int j = 0; j < 4; j++) {
            int col = tx * 4 + j;
            g_h1[(size_t)row * 64 + col] = acc[i][j] + bias[col];
        }
    }
}

// =====================================================================
// conv2: X = relu(a1*h1 + c1); X[64 x 64] @ W[64 x 128] + bias -> raw h2.
// =====================================================================
__global__ __launch_bounds__(256)
void conv2_kernel(const float* __restrict__ W, const float* __restrict__ bias) {
    __shared__ float Xs[64 * 64];    // 16 KB
    __shared__ float Ws[64 * 128];   // 32 KB  (total exactly 48 KB)
    const int row0 = blockIdx.x * 64;
    const int tid = threadIdx.x;

    for (int i = tid; i < 64 * 128; i += 256) Ws[i] = W[i];
    for (int i = tid; i < 64 * 64; i += 256) {
        int r = i >> 6, c = i & 63;
        float h = g_h1[(size_t)(row0 + r) * 64 + c];
        Xs[i] = fmaxf(0.0f, fmaf(g_a[c], h, g_c[c]));
    }
    __syncthreads();

    const int ty = tid >> 4, tx = tid & 15;
    float acc[4][8];
#pragma unroll
    for (int i = 0; i < 4; i++)
#pragma unroll
        for (int j = 0; j < 8; j++) acc[i][j] = 0.0f;

#pragma unroll 8
    for (int k = 0; k < 64; k++) {
        float xv[4];
#pragma unroll
        for (int i = 0; i < 4; i++) xv[i] = Xs[(ty * 4 + i) * 64 + k];
        float4 w0 = *(const float4*)&Ws[k * 128 + tx * 8];
        float4 w1 = *(const float4*)&Ws[k * 128 + tx * 8 + 4];
#pragma unroll
        for (int i = 0; i < 4; i++) {
            acc[i][0] = fmaf(xv[i], w0.x, acc[i][0]);
            acc[i][1] = fmaf(xv[i], w0.y, acc[i][1]);
            acc[i][2] = fmaf(xv[i], w0.z, acc[i][2]);
            acc[i][3] = fmaf(xv[i], w0.w, acc[i][3]);
            acc[i][4] = fmaf(xv[i], w1.x, acc[i][4]);
            acc[i][5] = fmaf(xv[i], w1.y, acc[i][5]);
            acc[i][6] = fmaf(xv[i], w1.z, acc[i][6]);
            acc[i][7] = fmaf(xv[i], w1.w, acc[i][7]);
        }
    }
#pragma unroll
    for (int i = 0; i < 4; i++) {
        int row = row0 + ty * 4 + i;
#pragma unroll
        for (int j = 0; j < 8; j++) {
            int col = tx * 8 + j;
            g_h2[(size_t)row * 128 + col] = acc[i][j] + bias[col];
        }
    }
}

// =====================================================================
// BN stats pass 1: fixed-order fp32 partials per (block, channel).
// grid = STAT_BLKS blocks of C threads.
// =====================================================================
__global__ void stats_kernel(const float* __restrict__ h, int C) {
    const int blk = blockIdx.x;
    const int tid = threadIdx.x;       // channel
    float s = 0.0f, ss = 0.0f;
    size_t base = (size_t)blk * ROWS_PER_STAT;
    for (int r = 0; r < ROWS_PER_STAT; r++) {
        float v = h[(base + r) * C + tid];
        s += v;
        ss += v * v;
    }
    g_part[(blk * C + tid) * 2 + 0] = s;
    g_part[(blk * C + tid) * 2 + 1] = ss;
}

// BN stats pass 2: fp64 fixed-order reduce -> affine (a, c).
__global__ void finalize_stats(const float* __restrict__ gamma,
                               const float* __restrict__ beta, int C) {
    const int tid = threadIdx.x;       // channel, blockDim = C
    double S = 0.0, SS = 0.0;
    for (int b = 0; b < STAT_BLKS; b++) {
        S  += (double)g_part[(b * C + tid) * 2 + 0];
        SS += (double)g_part[(b * C + tid) * 2 + 1];
    }
    double inv_n = 1.0 / (double)NROWS;
    double mu  = S * inv_n;
    double var = SS * inv_n - mu * mu;
    double a = (double)gamma[tid] / sqrt(var + 1e-5);
    g_a[tid] = (float)a;
    g_c[tid] = (float)((double)beta[tid] - mu * a);
}

// =====================================================================
// maxpool over K + BN affine + relu. Affine is monotone, so
// max(relu(a*h+c)) = relu(a*max(h)+c) for a>=0 (min for a<0) — bitwise exact.
// =====================================================================
__global__ void maxout_kernel(float* __restrict__ out) {
    const int cc = blockIdx.x;
    const int ch = threadIdx.x;        // 128 threads
    float mx = -3.402823466e38f, mn = 3.402823466e38f;
#pragma unroll 4
    for (int k = 0; k < 32; k++) {
        float v = g_h2[((size_t)cc * 32 + k) * 128 + ch];
        mx = fmaxf(mx, v);
        mn = fminf(mn, v);
    }
    float a = g_a[ch];
    float ext = (a >= 0.0f) ? mx : mn;
    out[(size_t)cc * 128 + ch] = fmaxf(0.0f, fmaf(a, ext, g_c[ch]));
}

// =====================================================================
extern "C" void kernel_launch(void* const* d_in, const int* in_sizes, int n_in,
                              void* d_out, int out_size) {
    const float* pos     = (const float*)d_in[0];
    const float* feat    = (const float*)d_in[1];
    const float* w_sem1  = (const float*)d_in[2];
    const float* b_sem1  = (const float*)d_in[3];
    const float* g_sem1  = (const float*)d_in[4];
    const float* be_sem1 = (const float*)d_in[5];
    const float* w_sem2  = (const float*)d_in[6];
    const float* b_sem2  = (const float*)d_in[7];
    const float* g_sem2  = (const float*)d_in[8];
    const float* be_sem2 = (const float*)d_in[9];
    const float* w_geo1  = (const float*)d_in[10];
    const float* b_geo1  = (const float*)d_in[11];
    const float* g_geo1  = (const float*)d_in[12];
    const float* be_geo1 = (const float*)d_in[13];
    const float* w_geo2  = (const float*)d_in[14];
    const float* b_geo2  = (const float*)d_in[15];
    const float* g_geo2  = (const float*)d_in[16];
    const float* be_geo2 = (const float*)d_in[17];
    float* out = (float*)d_out;

    // FPS needs 192 KB dynamic SMEM (opt-in beyond 48 KB).
    cudaFuncSetAttribute(fps_kernel, cudaFuncAttributeMaxDynamicSharedMemorySize,
                         3 * N_ * (int)sizeof(float));

    // Device scratch pointers (for kernels taking generic h pointers).
    float *h1p = nullptr, *h2p = nullptr;
    cudaGetSymbolAddress((void**)&h1p, g_h1);
    cudaGetSymbolAddress((void**)&h2p, g_h2);

    fps_kernel<<<B_, 1024, 3 * N_ * sizeof(float)>>>(pos);
    ballquery_kernel<<<NCC / 8, 256>>>(pos);

    // ---- SEM branch ----
    conv1_kernel<64, false><<<NROWS / 64, 256>>>(feat, nullptr, w_sem1, b_sem1);
    stats_kernel<<<STAT_BLKS, 64>>>(h1p, 64);
    finalize_stats<<<1, 64>>>(g_sem1, be_sem1, 64);
    conv2_kernel<<<NROWS / 64, 256>>>(w_sem2, b_sem2);
    stats_kernel<<<STAT_BLKS, 128>>>(h2p, 128);
    finalize_stats<<<1, 128>>>(g_sem2, be_sem2, 128);
    maxout_kernel<<<NCC, 128>>>(out);

    // ---- GEO branch (reuses g_h1/g_h2/g_part/g_a/g_c sequentially) ----
    conv1_kernel<6, true><<<NROWS / 64, 256>>>(nullptr, pos, w_geo1, b_geo1);
    stats_kernel<<<STAT_BLKS, 64>>>(h1p, 64);
    finalize_stats<<<1, 64>>>(g_geo1, be_geo1, 64);
    conv2_kernel<<<NROWS / 64, 256>>>(w_geo2, b_geo2);
    stats_kernel<<<STAT_BLKS, 128>>>(h2p, 128);
    finalize_stats<<<1, 128>>>(g_geo2, be_geo2, 128);
    maxout_kernel<<<NCC, 128>>>(out + (size_t)NCC * 128);
}

// round 6
// speedup vs baseline: 2.0347x; 2.0347x over previous
#include <cuda_runtime.h>
#include <cstdint>
#include <cstddef>

#define B_ 8
#define N_ 16384
#define S_ 1024
#define K_ 32
#define NCC (B_*S_)                 // 8192 centers
#define NROWS (NCC*K_)              // 262144 grouped rows
#define R2_ 0.04f
#define CBLKS (NROWS/64)            // 4096 conv blocks (64 rows each)

// ---------------- device scratch (static; allocation APIs banned) ----------------
__device__ __align__(16) float g_centers[NCC*3];
__device__ int                 g_nbr[NROWS];
__device__ __align__(16) float g_h1[(size_t)NROWS*64];          // 64 MiB (reused sem/geo)
__device__ __align__(16) float g_part[(size_t)CBLKS*128*2];     // per-block (sum,sumsq)
__device__ __align__(16) float g_mx[(size_t)NCC*128];           // per-center raw-h2 max
__device__ __align__(16) float g_mn[(size_t)NCC*128];           // per-center raw-h2 min
__device__ __align__(16) float g_a[128];                        // BN scale
__device__ __align__(16) float g_c[128];                        // BN shift

// ---------------- cluster SMEM helpers ----------------
__device__ __forceinline__ uint32_t s2u(const void* p) {
    return (uint32_t)__cvta_generic_to_shared(p);
}
__device__ __forceinline__ uint32_t mapa_u32(uint32_t a, int r) {
    uint32_t ret;
    asm("mapa.shared::cluster.u32 %0, %1, %2;" : "=r"(ret) : "r"(a), "r"(r));
    return ret;
}
__device__ __forceinline__ void st_rem64(uint32_t a, unsigned long long v) {
    asm volatile("st.shared::cluster.u64 [%0], %1;" :: "r"(a), "l"(v) : "memory");
}
__device__ __forceinline__ void st_rem32(uint32_t a, uint32_t v) {
    asm volatile("st.shared::cluster.b32 [%0], %1;" :: "r"(a), "r"(v) : "memory");
}

// =====================================================================
// FPS: 8-CTA cluster per batch, 512 thr/CTA, 4 points/thread in REGISTERS.
// Winner coords ride along the reduction; one cluster barrier per step.
// =====================================================================
#define FPS_C 8
#define FPS_T 512

__global__ __launch_bounds__(FPS_T, 1) __cluster_dims__(FPS_C, 1, 1)
void fps_kernel(const float* __restrict__ pos) {
    __shared__ unsigned long long wkey[16];
    __shared__ float wx[16], wy[16], wz[16];
    __shared__ unsigned long long pkey[2][FPS_C];
    __shared__ float pxx[2][FPS_C], pyy[2][FPS_C], pzz[2][FPS_C];

    const int rank = blockIdx.x & (FPS_C - 1);
    const int b    = blockIdx.x >> 3;
    const int tid  = threadIdx.x;
    const int lane = tid & 31, wid = tid >> 5;
    const float* p = pos + (size_t)b * N_ * 3;

    float qx[4], qy[4], qz[4], dist[4];
#pragma unroll
    for (int j = 0; j < 4; j++) {
        int g = rank * 2048 + j * FPS_T + tid;
        qx[j] = p[g*3]; qy[j] = p[g*3+1]; qz[j] = p[g*3+2];
        dist[j] = 1e10f;
    }
    float cx = p[0], cy = p[1], cz = p[2];   // far_0 = 0

    for (int s = 0; s < S_; s++) {
        if (rank == 0 && tid == 0) {
            size_t cc = (size_t)b * S_ + s;
            g_centers[cc*3+0] = cx; g_centers[cc*3+1] = cy; g_centers[cc*3+2] = cz;
        }
        if (s == S_ - 1) break;

        // ---- update dists + local argmax (coords tracked alongside) ----
        float best = -1.0f, bx = 0.f, by = 0.f, bz = 0.f;
        int bidx = 0;
#pragma unroll
        for (int j = 0; j < 4; j++) {
            float dx = qx[j] - cx, dy = qy[j] - cy, dz = qz[j] - cz;
            float d  = fmaf(dz, dz, fmaf(dy, dy, dx * dx));
            float nd = fminf(dist[j], d);
            dist[j]  = nd;
            if (nd > best) { best = nd; bx = qx[j]; by = qy[j]; bz = qz[j];
                             bidx = rank * 2048 + j * FPS_T + tid; }
        }
        // key: hi32 = dist bits (positive floats order-isomorphic), lo32 = N-idx
        // (max-key => largest dist, smallest index on ties; indices unique => no key ties)
        unsigned long long key =
            ((unsigned long long)__float_as_uint(best) << 32) | (unsigned)(N_ - bidx);

        // ---- warp reduce (key + coords) ----
#pragma unroll
        for (int o = 16; o; o >>= 1) {
            unsigned long long k2 = __shfl_down_sync(0xFFFFFFFFu, key, o);
            float x2 = __shfl_down_sync(0xFFFFFFFFu, bx, o);
            float y2 = __shfl_down_sync(0xFFFFFFFFu, by, o);
            float z2 = __shfl_down_sync(0xFFFFFFFFu, bz, o);
            if (k2 > key) { key = k2; bx = x2; by = y2; bz = z2; }
        }
        if (lane == 0) { wkey[wid] = key; wx[wid] = bx; wy[wid] = by; wz[wid] = bz; }
        __syncthreads();

        const int par = s & 1;
        if (tid < 32) {
            key = (lane < 16) ? wkey[lane] : 0ull;   // 0 never wins (lo32 of real keys > 0)
            bx = wx[lane & 15]; by = wy[lane & 15]; bz = wz[lane & 15];
#pragma unroll
            for (int o = 8; o; o >>= 1) {
                unsigned long long k2 = __shfl_down_sync(0xFFFFFFFFu, key, o);
                float x2 = __shfl_down_sync(0xFFFFFFFFu, bx, o);
                float y2 = __shfl_down_sync(0xFFFFFFFFu, by, o);
                float z2 = __shfl_down_sync(0xFFFFFFFFu, bz, o);
                if (k2 > key) { key = k2; bx = x2; by = y2; bz = z2; }
            }
            if (lane == 0) {
                // publish this CTA's winner into slot[rank] of every cluster peer
                uint32_t ak = s2u(&pkey[par][rank]);
                uint32_t ax = s2u(&pxx[par][rank]);
                uint32_t ay = s2u(&pyy[par][rank]);
                uint32_t az = s2u(&pzz[par][rank]);
#pragma unroll
                for (int r = 0; r < FPS_C; r++) {
                    st_rem64(mapa_u32(ak, r), key);
                    st_rem32(mapa_u32(ax, r), __float_as_uint(bx));
                    st_rem32(mapa_u32(ay, r), __float_as_uint(by));
                    st_rem32(mapa_u32(az, r), __float_as_uint(bz));
                }
            }
        }
        // one cluster barrier per step (double-buffered slots make it sufficient)
        asm volatile("barrier.cluster.arrive.aligned;" ::: "memory");
        asm volatile("barrier.cluster.wait.aligned;"   ::: "memory");

        // ---- every thread reduces the 8 published records locally ----
        unsigned long long wk = pkey[par][0];
        cx = pxx[par][0]; cy = pyy[par][0]; cz = pzz[par][0];
#pragma unroll
        for (int r = 1; r < FPS_C; r++) {
            unsigned long long k2 = pkey[par][r];
            if (k2 > wk) { wk = k2; cx = pxx[par][r]; cy = pyy[par][r]; cz = pzz[par][r]; }
        }
    }
}

// =====================================================================
// Ball query: one warp per center, ascending index scan, early exit.
// =====================================================================
__global__ __launch_bounds__(256)
void ballquery_kernel(const float* __restrict__ pos) {
    __shared__ int buf[8][32];
    const int wloc = threadIdx.x >> 5;
    const int lane = threadIdx.x & 31;
    const int cc = blockIdx.x * 8 + wloc;
    const int b = cc >> 10;
    const float* p = pos + (size_t)b * N_ * 3;
    const float cx = g_centers[cc*3], cy = g_centers[cc*3+1], cz = g_centers[cc*3+2];

    int count = 0, first = 0;
    bool haveFirst = false;
    for (int base = 0; base < N_; base += 32) {
        int j = base + lane;
        float x = p[j*3], y = p[j*3+1], z = p[j*3+2];
        float dx = cx - x, dy = cy - y, dz = cz - z;
        float d = fmaf(dz, dz, fmaf(dy, dy, dx * dx));
        bool in = (d <= R2_);
        unsigned m = __ballot_sync(0xFFFFFFFFu, in);
        if (m) {
            if (!haveFirst) { first = base + __ffs(m) - 1; haveFirst = true; }
            int slot = count + __popc(m & ((1u << lane) - 1u));
            if (in && slot < 32) buf[wloc][slot] = j;
            count += __popc(m);
            if (count >= 32) break;
        }
    }
    __syncwarp();
    int v = (lane < count) ? buf[wloc][lane] : first;
    g_nbr[(size_t)cc * 32 + lane] = v;
}

// =====================================================================
// conv1: gather + X[64 x CIN] @ W[CIN x 64] + bias -> raw h1.
// Epilogue: per-block per-channel (sum, sumsq) in fixed order -> g_part.
// =====================================================================
template<int CIN, bool GEO>
__global__ __launch_bounds__(256)
void conv1_kernel(const float* __restrict__ feat, const float* __restrict__ pos,
                  const float* __restrict__ W, const float* __restrict__ bias) {
    __shared__ float Xs[64 * CIN];
    __shared__ float Ws[CIN * 64];
    __shared__ float red[16 * 64];
    const int row0 = blockIdx.x * 64;
    const int tid = threadIdx.x;

    for (int i = tid; i < CIN * 64 / 4; i += 256)
        ((float4*)Ws)[i] = ((const float4*)W)[i];

    if (!GEO) {
        // CIN == 64: vectorized gather, 16 float4 per row
        for (int i = tid; i < 64 * 16; i += 256) {
            int r = i >> 4, c4 = (i & 15) * 4;
            int row = row0 + r;
            int j = g_nbr[row];
            int b = row >> 15;
            float4 v = *(const float4*)&feat[((size_t)b * N_ + j) * 64 + c4];
            *(float4*)&Xs[r * CIN + c4] = v;
        }
    } else {
        for (int i = tid; i < 64 * CIN; i += 256) {
            int r = i / CIN, c = i - r * CIN;
            int row = row0 + r;
            int cc = row >> 5;
            if (c < 3) {
                Xs[i] = g_centers[cc * 3 + c];
            } else {
                int j = g_nbr[row];
                int b = row >> 15;
                Xs[i] = pos[((size_t)b * N_ + j) * 3 + (c - 3)];
            }
        }
    }
    __syncthreads();

    const int ty = tid >> 4, tx = tid & 15;
    float acc[4][4];
#pragma unroll
    for (int i = 0; i < 4; i++)
#pragma unroll
        for (int j = 0; j < 4; j++) acc[i][j] = 0.0f;

#pragma unroll
    for (int k = 0; k < CIN; k++) {
        float xv[4];
#pragma unroll
        for (int i = 0; i < 4; i++) xv[i] = Xs[(ty * 4 + i) * CIN + k];
        float4 wv = *(const float4*)&Ws[k * 64 + tx * 4];
#pragma unroll
        for (int i = 0; i < 4; i++) {
            acc[i][0] = fmaf(xv[i], wv.x, acc[i][0]);
            acc[i][1] = fmaf(xv[i], wv.y, acc[i][1]);
            acc[i][2] = fmaf(xv[i], wv.z, acc[i][2]);
            acc[i][3] = fmaf(xv[i], wv.w, acc[i][3]);
        }
    }

    // write h1 + accumulate local stats (fixed order i=0..3)
    float bb[4];
#pragma unroll
    for (int j = 0; j < 4; j++) bb[j] = bias[tx * 4 + j];
    float sl[4] = {0, 0, 0, 0}, ssl[4] = {0, 0, 0, 0};
#pragma unroll
    for (int i = 0; i < 4; i++) {
        int row = row0 + ty * 4 + i;
        float4 hv;
        hv.x = acc[i][0] + bb[0]; hv.y = acc[i][1] + bb[1];
        hv.z = acc[i][2] + bb[2]; hv.w = acc[i][3] + bb[3];
        *(float4*)&g_h1[(size_t)row * 64 + tx * 4] = hv;
        sl[0] += hv.x; ssl[0] += hv.x * hv.x;
        sl[1] += hv.y; ssl[1] += hv.y * hv.y;
        sl[2] += hv.z; ssl[2] += hv.z * hv.z;
        sl[3] += hv.w; ssl[3] += hv.w * hv.w;
    }
    // fixed-order cross-thread reduce over ty (deterministic)
#pragma unroll
    for (int j = 0; j < 4; j++) red[ty * 64 + tx * 4 + j] = sl[j];
    __syncthreads();
    float S = 0.0f, SS = 0.0f;
    if (tid < 64) {
#pragma unroll
        for (int t = 0; t < 16; t++) S += red[t * 64 + tid];
    }
    __syncthreads();
#pragma unroll
    for (int j = 0; j < 4; j++) red[ty * 64 + tx * 4 + j] = ssl[j];
    __syncthreads();
    if (tid < 64) {
#pragma unroll
        for (int t = 0; t < 16; t++) SS += red[t * 64 + tid];
        g_part[((size_t)blockIdx.x * 64 + tid) * 2 + 0] = S;
        g_part[((size_t)blockIdx.x * 64 + tid) * 2 + 1] = SS;
    }
}

// =====================================================================
// conv2 (fused): X = relu(a1*h1 + c1); X[64x64] @ W[64x128] + bias.
// h2 is NEVER written. Epilogue: per-block channel (sum,sumsq) and
// per-center (2 per block) raw max/min -> g_mx/g_mn. Fixed order.
// =====================================================================
__global__ __launch_bounds__(256)
void conv2_kernel(const float* __restrict__ W, const float* __restrict__ bias) {
    __shared__ float Xs[64 * 64];    // 16 KB (reused as reduce buffer)
    __shared__ float Ws[64 * 128];   // 32 KB
    const int row0 = blockIdx.x * 64;
    const int tid = threadIdx.x;

    for (int i = tid; i < 64 * 128 / 4; i += 256)
        ((float4*)Ws)[i] = ((const float4*)W)[i];
    for (int i = tid; i < 64 * 16; i += 256) {
        int r = i >> 4, c4 = (i & 15) * 4;
        float4 h = *(const float4*)&g_h1[(size_t)(row0 + r) * 64 + c4];
        float4 A = *(const float4*)&g_a[c4];
        float4 C = *(const float4*)&g_c[c4];
        float4 x;
        x.x = fmaxf(0.0f, fmaf(A.x, h.x, C.x));
        x.y = fmaxf(0.0f, fmaf(A.y, h.y, C.y));
        x.z = fmaxf(0.0f, fmaf(A.z, h.z, C.z));
        x.w = fmaxf(0.0f, fmaf(A.w, h.w, C.w));
        *(float4*)&Xs[r * 64 + c4] = x;
    }
    __syncthreads();

    const int ty = tid >> 4, tx = tid & 15;
    float acc[4][8];
#pragma unroll
    for (int i = 0; i < 4; i++)
#pragma unroll
        for (int j = 0; j < 8; j++) acc[i][j] = 0.0f;

#pragma unroll 8
    for (int k = 0; k < 64; k++) {
        float xv[4];
#pragma unroll
        for (int i = 0; i < 4; i++) xv[i] = Xs[(ty * 4 + i) * 64 + k];
        float4 w0 = *(const float4*)&Ws[k * 128 + tx * 8];
        float4 w1 = *(const float4*)&Ws[k * 128 + tx * 8 + 4];
#pragma unroll
        for (int i = 0; i < 4; i++) {
            acc[i][0] = fmaf(xv[i], w0.x, acc[i][0]);
            acc[i][1] = fmaf(xv[i], w0.y, acc[i][1]);
            acc[i][2] = fmaf(xv[i], w0.z, acc[i][2]);
            acc[i][3] = fmaf(xv[i], w0.w, acc[i][3]);
            acc[i][4] = fmaf(xv[i], w1.x, acc[i][4]);
            acc[i][5] = fmaf(xv[i], w1.y, acc[i][5]);
            acc[i][6] = fmaf(xv[i], w1.z, acc[i][6]);
            acc[i][7] = fmaf(xv[i], w1.w, acc[i][7]);
        }
    }

    // local epilogue stats (thread rows all in one center: ty<8 -> A, ty>=8 -> B)
    float bb[8];
#pragma unroll
    for (int j = 0; j < 8; j++) bb[j] = bias[tx * 8 + j];
    float sl[8], ssl[8], mxl[8], mnl[8];
#pragma unroll
    for (int j = 0; j < 8; j++) {
        sl[j] = 0.0f; ssl[j] = 0.0f;
        mxl[j] = -3.402823466e38f; mnl[j] = 3.402823466e38f;
    }
#pragma unroll
    for (int i = 0; i < 4; i++)
#pragma unroll
        for (int j = 0; j < 8; j++) {
            float h = acc[i][j] + bb[j];
            sl[j] += h; ssl[j] += h * h;
            mxl[j] = fmaxf(mxl[j], h); mnl[j] = fminf(mnl[j], h);
        }

    float* red = Xs;                 // reuse (all mainloop reads done after sync)
    __syncthreads();

    float S = 0.0f, SS = 0.0f, mA = 0.0f, mB = 0.0f, nA = 0.0f, nB = 0.0f;
#pragma unroll
    for (int j = 0; j < 8; j++) red[ty * 128 + tx * 8 + j] = sl[j];
    __syncthreads();
    if (tid < 128) {
#pragma unroll
        for (int t = 0; t < 16; t++) S += red[t * 128 + tid];
    }
    __syncthreads();
#pragma unroll
    for (int j = 0; j < 8; j++) red[ty * 128 + tx * 8 + j] = ssl[j];
    __syncthreads();
    if (tid < 128) {
#pragma unroll
        for (int t = 0; t < 16; t++) SS += red[t * 128 + tid];
    }
    __syncthreads();
#pragma unroll
    for (int j = 0; j < 8; j++) red[ty * 128 + tx * 8 + j] = mxl[j];
    __syncthreads();
    if (tid < 128) {
        mA = red[0 * 128 + tid]; mB = red[8 * 128 + tid];
#pragma unroll
        for (int t = 1; t < 8; t++) { mA = fmaxf(mA, red[t * 128 + tid]);
                                      mB = fmaxf(mB, red[(8 + t) * 128 + tid]); }
    }
    __syncthreads();
#pragma unroll
    for (int j = 0; j < 8; j++) red[ty * 128 + tx * 8 + j] = mnl[j];
    __syncthreads();
    if (tid < 128) {
        nA = red[0 * 128 + tid]; nB = red[8 * 128 + tid];
#pragma unroll
        for (int t = 1; t < 8; t++) { nA = fminf(nA, red[t * 128 + tid]);
                                      nB = fminf(nB, red[(8 + t) * 128 + tid]); }
        int blk = blockIdx.x;
        g_part[((size_t)blk * 128 + tid) * 2 + 0] = S;
        g_part[((size_t)blk * 128 + tid) * 2 + 1] = SS;
        g_mx[(size_t)(blk * 2 + 0) * 128 + tid] = mA;
        g_mx[(size_t)(blk * 2 + 1) * 128 + tid] = mB;
        g_mn[(size_t)(blk * 2 + 0) * 128 + tid] = nA;
        g_mn[(size_t)(blk * 2 + 1) * 128 + tid] = nB;
    }
}

// =====================================================================
// BN finalize: one block per channel; fp64 fixed-order tree over 4096
// per-block partials -> affine (a, c).
// =====================================================================
__global__ __launch_bounds__(256)
void finalize_stats(const float* __restrict__ gamma,
                    const float* __restrict__ beta, int C) {
    const int ch = blockIdx.x;
    const int t = threadIdx.x;     // 256
    __shared__ double rs[256], rss[256];
    double S = 0.0, SS = 0.0;
#pragma unroll 4
    for (int i = 0; i < 16; i++) {
        int blk = t * 16 + i;      // fixed order
        S  += (double)g_part[((size_t)blk * C + ch) * 2 + 0];
        SS += (double)g_part[((size_t)blk * C + ch) * 2 + 1];
    }
    rs[t] = S; rss[t] = SS;
    __syncthreads();
    for (int off = 128; off; off >>= 1) {
        if (t < off) { rs[t] += rs[t + off]; rss[t] += rss[t + off]; }
        __syncthreads();
    }
    if (t == 0) {
        double inv_n = 1.0 / (double)NROWS;
        double mu  = rs[0] * inv_n;
        double var = rss[0] * inv_n - mu * mu;
        double a = (double)gamma[ch] / sqrt(var + 1e-5);
        g_a[ch] = (float)a;
        g_c[ch] = (float)((double)beta[ch] - mu * a);
    }
}

// =====================================================================
// Output: relu(a * extreme(h2) + c). Affine monotone => commutes with max.
// =====================================================================
__global__ void final_out(float* __restrict__ out) {
    const int cc = blockIdx.x;
    const int ch = threadIdx.x;    // 128
    float a = g_a[ch];
    float ext = (a >= 0.0f) ? g_mx[(size_t)cc * 128 + ch] : g_mn[(size_t)cc * 128 + ch];
    out[(size_t)cc * 128 + ch] = fmaxf(0.0f, fmaf(a, ext, g_c[ch]));
}

// =====================================================================
extern "C" void kernel_launch(void* const* d_in, const int* in_sizes, int n_in,
                              void* d_out, int out_size) {
    const float* pos     = (const float*)d_in[0];
    const float* feat    = (const float*)d_in[1];
    const float* w_sem1  = (const float*)d_in[2];
    const float* b_sem1  = (const float*)d_in[3];
    const float* g_sem1  = (const float*)d_in[4];
    const float* be_sem1 = (const float*)d_in[5];
    const float* w_sem2  = (const float*)d_in[6];
    const float* b_sem2  = (const float*)d_in[7];
    const float* g_sem2  = (const float*)d_in[8];
    const float* be_sem2 = (const float*)d_in[9];
    const float* w_geo1  = (const float*)d_in[10];
    const float* b_geo1  = (const float*)d_in[11];
    const float* g_geo1  = (const float*)d_in[12];
    const float* be_geo1 = (const float*)d_in[13];
    const float* w_geo2  = (const float*)d_in[14];
    const float* b_geo2  = (const float*)d_in[15];
    const float* g_geo2  = (const float*)d_in[16];
    const float* be_geo2 = (const float*)d_in[17];
    float* out = (float*)d_out;

    fps_kernel<<<B_ * FPS_C, FPS_T>>>(pos);
    ballquery_kernel<<<NCC / 8, 256>>>(pos);

    // ---- SEM branch ----
    conv1_kernel<64, false><<<CBLKS, 256>>>(feat, nullptr, w_sem1, b_sem1);
    finalize_stats<<<64, 256>>>(g_sem1, be_sem1, 64);
    conv2_kernel<<<CBLKS, 256>>>(w_sem2, b_sem2);
    finalize_stats<<<128, 256>>>(g_sem2, be_sem2, 128);
    final_out<<<NCC, 128>>>(out);

    // ---- GEO branch (reuses scratch sequentially; stream-ordered) ----
    conv1_kernel<6, true><<<CBLKS, 256>>>(nullptr, pos, w_geo1, b_geo1);
    finalize_stats<<<64, 256>>>(g_geo1, be_geo1, 64);
    conv2_kernel<<<CBLKS, 256>>>(w_geo2, b_geo2);
    finalize_stats<<<128, 256>>>(g_geo2, be_geo2, 128);
    final_out<<<NCC, 128>>>(out + (size_t)NCC * 128);
}